// round 6
// baseline (speedup 1.0000x reference)
#include <cuda_runtime.h>
#include <cstdint>

#define NN 4096
#define CC 8
#define BB 2
#define PP 16          // B*C
#define MAXDET 100
#define SCORE_THR 0.01f

// ---------------- static scratch (no runtime allocation allowed) ----------------
__device__ unsigned int       g_sortedIdx[PP][NN];
__device__ unsigned int       g_sortedOrd[PP][NN];
__device__ int                g_V[PP];
__device__ unsigned long long g_cand[BB][CC * MAXDET];   // fully rewritten every launch

// float -> monotone unsigned (ascending order)
__device__ __forceinline__ unsigned int ford(float f) {
    unsigned int u = __float_as_uint(f);
    return (u & 0x80000000u) ? ~u : (u | 0x80000000u);
}

// exact replica of: fl(inter / max(union,1e-9)) > 0.5   (reference fp32 rounding)
__device__ __forceinline__ bool iou_gt_half(float4 a, float aa, float4 b, float ab) {
    float ix1 = fmaxf(a.x, b.x);
    float iy1 = fmaxf(a.y, b.y);
    float ix2 = fminf(a.z, b.z);
    float iy2 = fminf(a.w, b.w);
    float iw = fmaxf(ix2 - ix1, 0.0f);
    float ih = fmaxf(iy2 - iy1, 0.0f);
    float inter = iw * ih;
    float uni = (aa + ab) - inter;
    float d = fmaf(-0.5f, uni, inter);        // sign is exact
    bool gt = d > 0.0f;
    if (fabsf(d) <= 1e-5f * uni) {            // borderline: do the real division
        gt = __fdiv_rn(inter, fmaxf(uni, 1e-9f)) > 0.5f;
    }
    return gt;
}

// -------- Stage A: per-(b,c) stable sort by masked score (desc), via u64 keys ----
__global__ __launch_bounds__(1024) void sort_kernel(const float* __restrict__ cls) {
    int p = blockIdx.x;          // 0..15
    int b = p >> 3;
    int c = p & 7;
    __shared__ unsigned long long sk[NN];
    __shared__ int sV;
    int tid = threadIdx.x;
    if (tid == 0) sV = 0;
    __syncthreads();

    int localValid = 0;
    for (int n = tid; n < NN; n += 1024) {
        float s = cls[(((b << 12) + n) << 3) + c];
        bool valid = s > SCORE_THR;
        // masked = valid ? s : -1e30 ; ascending key on -masked == score descending
        unsigned int hi = valid ? ford(-s) : ford(1e30f);
        sk[n] = ((unsigned long long)hi << 32) | (unsigned int)n;
        localValid += valid ? 1 : 0;
    }
    atomicAdd(&sV, localValid);
    __syncthreads();

    // bitonic sort ascending, 4096 elems, 1024 threads
    for (int k = 2; k <= NN; k <<= 1) {
        for (int j = k >> 1; j > 0; j >>= 1) {
            for (int t = tid; t < NN; t += 1024) {
                int ixj = t ^ j;
                if (ixj > t) {
                    unsigned long long a = sk[t], d = sk[ixj];
                    bool asc = ((t & k) == 0);
                    bool sw = asc ? (a > d) : (a < d);
                    if (sw) { sk[t] = d; sk[ixj] = a; }
                }
            }
            __syncthreads();
        }
    }

    for (int i = tid; i < NN; i += 1024) {
        unsigned long long key = sk[i];
        g_sortedIdx[p][i] = (unsigned int)(key & 0xffffffffu);
        g_sortedOrd[p][i] = (unsigned int)(key >> 32);
    }
    if (tid == 0) g_V[p] = sV;
}

// -------- Stage B: greedy NMS with early stop at MAXDET kept (1 warp / class) ----
__global__ __launch_bounds__(32) void nms_kernel(const float* __restrict__ boxes) {
    int p = blockIdx.x;
    int b = p >> 3;
    int c = p & 7;
    int lane = threadIdx.x;
    __shared__ float4 keptBox[MAXDET];
    __shared__ float  keptArea[MAXDET];

    const float4* bx4 = reinterpret_cast<const float4*>(boxes) + (b << 12);
    const unsigned int* sIdx = &g_sortedIdx[p][0];
    const unsigned int* sOrd = &g_sortedOrd[p][0];
    int V = g_V[p];
    int kept = 0;

    // 2-deep prefetch pipeline: idx/ord 2 ahead, box 1 ahead
    unsigned int nA = 0, nB = 0, oA = 0, oB = 0;
    float4 bA = make_float4(0.f, 0.f, 0.f, 0.f);
    if (V > 0) { nA = __ldg(&sIdx[0]); oA = __ldg(&sOrd[0]); bA = __ldg(&bx4[nA]); }
    if (V > 1) { nB = __ldg(&sIdx[1]); oB = __ldg(&sOrd[1]); }

    for (int j = 0; j < V && kept < MAXDET; j++) {
        unsigned int n = nA, ord = oA;
        float4 bj = bA;
        // issue prefetches for j+1 (box) and j+2 (idx/ord)
        float4 bNext = make_float4(0.f, 0.f, 0.f, 0.f);
        if (j + 1 < V) bNext = __ldg(&bx4[nB]);
        unsigned int nC = 0, oC = 0;
        if (j + 2 < V) { nC = __ldg(&sIdx[j + 2]); oC = __ldg(&sOrd[j + 2]); }

        float aj = (bj.z - bj.x) * (bj.w - bj.y);
        bool sup = false;
        for (int t = lane; t < kept; t += 32) {
            if (iou_gt_half(keptBox[t], keptArea[t], bj, aj)) sup = true;
        }
        unsigned int bal = __ballot_sync(0xffffffffu, sup);
        if (bal == 0u) {                       // kept
            if (lane == 0) {
                keptBox[kept] = bj;
                keptArea[kept] = aj;
                g_cand[b][c * MAXDET + kept] =
                    ((unsigned long long)ord << 32) | (unsigned int)((c << 12) | n);
            }
            kept++;
        }
        __syncwarp();                          // keptBox visible before next test

        nA = nB; oA = oB; bA = bNext;
        nB = nC; oB = oC;
    }

    // pad unused slots (keys sort last; decoded as "no detection")
    for (int t = kept + lane; t < MAXDET; t += 32)
        g_cand[b][c * MAXDET + t] = 0xFFFFFFFFFFFFFFFFull;
}

// -------- Stage C: per-batch sort of 800 candidates, top-100, write outputs ------
__global__ __launch_bounds__(1024) void topk_kernel(const float* __restrict__ boxes,
                                                    const float* __restrict__ rot,
                                                    const float* __restrict__ trans,
                                                    float* __restrict__ out) {
    int b = blockIdx.x;
    __shared__ unsigned long long s[1024];
    int tid = threadIdx.x;
    s[tid] = (tid < CC * MAXDET) ? g_cand[b][tid] : 0xFFFFFFFFFFFFFFFFull;
    __syncthreads();

    // bitonic sort ascending (best = smallest key first)
    for (int k = 2; k <= 1024; k <<= 1) {
        for (int j = k >> 1; j > 0; j >>= 1) {
            int ixj = tid ^ j;
            if (ixj > tid) {
                unsigned long long a = s[tid], d = s[ixj];
                bool asc = ((tid & k) == 0);
                bool sw = asc ? (a > d) : (a < d);
                if (sw) { s[tid] = d; s[ixj] = a; }
            }
            __syncthreads();
        }
    }

    if (tid < MAXDET) {
        unsigned long long key = s[tid];
        unsigned int hi = (unsigned int)(key >> 32);
        bool ok = (hi != 0xFFFFFFFFu);
        float b0 = -1.f, b1 = -1.f, b2 = -1.f, b3 = -1.f;
        float sc = -1.f, lab = -1.f;
        float r0 = -1.f, r1 = -1.f, r2 = -1.f;
        float t0 = -1.f, t1 = -1.f, t2 = -1.f;
        if (ok) {
            unsigned int flat = (unsigned int)(key & 0xffffffffu);
            int c = flat >> 12;
            int n = flat & (NN - 1);
            // hi = ford(-s) with -s < 0  =>  bits(-s) = ~hi  =>  s = -uint_as_float(~hi)
            sc = -__uint_as_float(~hi);
            lab = (float)c;
            float4 bb4 = reinterpret_cast<const float4*>(boxes)[(b << 12) + n];
            b0 = bb4.x; b1 = bb4.y; b2 = bb4.z; b3 = bb4.w;
            int base3 = ((b << 12) + n) * 3;
            r0 = rot[base3 + 0]; r1 = rot[base3 + 1]; r2 = rot[base3 + 2];
            t0 = trans[base3 + 0]; t1 = trans[base3 + 1]; t2 = trans[base3 + 2];
        }
        // output layout: boxes[B,100,4] | scores[B,100] | labels[B,100] | rot[B,100,3] | trans[B,100,3]
        int r = tid;
        float* obox = out;                       // 0    .. 800
        float* osc  = out + BB * MAXDET * 4;     // 800  .. 1000
        float* olab = osc + BB * MAXDET;         // 1000 .. 1200
        float* orot = olab + BB * MAXDET;        // 1200 .. 1800
        float* otr  = orot + BB * MAXDET * 3;    // 1800 .. 2400
        obox[(b * MAXDET + r) * 4 + 0] = b0;
        obox[(b * MAXDET + r) * 4 + 1] = b1;
        obox[(b * MAXDET + r) * 4 + 2] = b2;
        obox[(b * MAXDET + r) * 4 + 3] = b3;
        osc[b * MAXDET + r] = sc;
        olab[b * MAXDET + r] = lab;
        orot[(b * MAXDET + r) * 3 + 0] = r0;
        orot[(b * MAXDET + r) * 3 + 1] = r1;
        orot[(b * MAXDET + r) * 3 + 2] = r2;
        otr[(b * MAXDET + r) * 3 + 0] = t0;
        otr[(b * MAXDET + r) * 3 + 1] = t1;
        otr[(b * MAXDET + r) * 3 + 2] = t2;
    }
}

extern "C" void kernel_launch(void* const* d_in, const int* in_sizes, int n_in,
                              void* d_out, int out_size) {
    const float* boxes = (const float*)d_in[0];
    const float* cls   = (const float*)d_in[1];
    const float* rot   = (const float*)d_in[2];
    const float* trans = (const float*)d_in[3];
    float* out = (float*)d_out;
    (void)in_sizes; (void)n_in; (void)out_size;

    sort_kernel<<<PP, 1024>>>(cls);
    nms_kernel<<<PP, 32>>>(boxes);
    topk_kernel<<<BB, 1024>>>(boxes, rot, trans, out);
}

// round 7
// speedup vs baseline: 1.2471x; 1.2471x over previous
#include <cuda_runtime.h>
#include <cstdint>
#include <cub/block/block_radix_sort.cuh>

#define NN 4096
#define CC 8
#define BB 2
#define PP 16          // B*C
#define MAXDET 100
#define SCORE_THR 0.01f

// ---------------- static scratch (no runtime allocation allowed) ----------------
// cand key layout: [ord:32 | c:3 | n:12]  (47 bits) ; pad = ~0ull
__device__ unsigned long long g_cand[BB][CC * MAXDET];

// float -> monotone unsigned (ascending order)
__device__ __forceinline__ unsigned int ford(float f) {
    unsigned int u = __float_as_uint(f);
    return (u & 0x80000000u) ? ~u : (u | 0x80000000u);
}

// exact replica of: fl(inter / max(union,1e-9)) > 0.5   (reference fp32 rounding)
__device__ __forceinline__ bool iou_gt_half(float4 a, float aa, float4 b, float ab) {
    float ix1 = fmaxf(a.x, b.x);
    float iy1 = fmaxf(a.y, b.y);
    float ix2 = fminf(a.z, b.z);
    float iy2 = fminf(a.w, b.w);
    float iw = fmaxf(ix2 - ix1, 0.0f);
    float ih = fmaxf(iy2 - iy1, 0.0f);
    float inter = iw * ih;
    float uni = (aa + ab) - inter;
    float d = fmaf(-0.5f, uni, inter);        // sign is exact
    bool gt = d > 0.0f;
    if (fabsf(d) <= 1e-5f * uni) {            // borderline: do the real division
        gt = __fdiv_rn(inter, fmaxf(uni, 1e-9f)) > 0.5f;
    }
    return gt;
}

using BlockSort = cub::BlockRadixSort<unsigned long long, 1024, 4>;

// ---- fused: radix sort by (scoreOrd, idx) + early-stop greedy NMS (warp 0) ------
__global__ __launch_bounds__(1024) void sortnms_kernel(const float* __restrict__ cls,
                                                       const float* __restrict__ boxes) {
    extern __shared__ char dyn[];
    unsigned long long* skeys = reinterpret_cast<unsigned long long*>(dyn);        // 32 KB
    typename BlockSort::TempStorage* cubTmp =
        reinterpret_cast<typename BlockSort::TempStorage*>(dyn + NN * 8);

    int p = blockIdx.x;          // 0..15
    int b = p >> 3;
    int c = p & 7;
    int tid = threadIdx.x;

    // build 44-bit keys: [ford(-s):32 | n:12], invalid -> hi=0xFFFFFFFF (sorts last)
    unsigned long long keys[4];
#pragma unroll
    for (int e = 0; e < 4; e++) {
        int n = tid * 4 + e;
        float s = cls[(((b << 12) + n) << 3) + c];
        unsigned int hi = (s > SCORE_THR) ? ford(-s) : 0xFFFFFFFFu;
        keys[e] = ((unsigned long long)hi << 12) | (unsigned int)n;
    }

    BlockSort(*cubTmp).Sort(keys, 0, 44);

#pragma unroll
    for (int e = 0; e < 4; e++) skeys[tid * 4 + e] = keys[e];
    __syncthreads();

    if (tid >= 32) return;       // warp 0 does the (serial) NMS scan
    int lane = tid;

    const float4* bx4 = reinterpret_cast<const float4*>(boxes) + (b << 12);

    // kept set in registers: lane holds kept indices k with (k&31)==lane, slot k>>5
    float4 kb0, kb1, kb2, kb3;
    float ka0 = 0.f, ka1 = 0.f, ka2 = 0.f, ka3 = 0.f;
    kb0 = kb1 = kb2 = kb3 = make_float4(0.f, 0.f, 0.f, 0.f);
    int kept = 0;

    // 2-deep prefetch pipeline
    unsigned long long keyA = skeys[0];
    unsigned long long keyB = skeys[1];
    float4 bA = __ldg(&bx4[(int)(keyA & 4095u)]);

    for (int j = 0; j < NN && kept < MAXDET; j++) {
        unsigned long long key = keyA;
        if ((unsigned int)(key >> 12) == 0xFFFFFFFFu) break;   // rest invalid
        float4 bj = bA;

        // prefetch j+1 box and j+2 key
        float4 bN = __ldg(&bx4[(int)(keyB & 4095u)]);
        unsigned long long keyC = (j + 2 < NN) ? skeys[j + 2] : ~0ull;

        float aj = (bj.z - bj.x) * (bj.w - bj.y);

        bool sup = false;
        if (lane      < kept) sup |= iou_gt_half(kb0, ka0, bj, aj);
        if (lane + 32 < kept) sup |= iou_gt_half(kb1, ka1, bj, aj);
        if (lane + 64 < kept) sup |= iou_gt_half(kb2, ka2, bj, aj);
        if (lane + 96 < kept) sup |= iou_gt_half(kb3, ka3, bj, aj);
        unsigned int bal = __ballot_sync(0xffffffffu, sup);

        if (bal == 0u) {                           // kept
            int slot = kept >> 5;
            if (lane == (kept & 31)) {
                switch (slot) {
                    case 0: kb0 = bj; ka0 = aj; break;
                    case 1: kb1 = bj; ka1 = aj; break;
                    case 2: kb2 = bj; ka2 = aj; break;
                    default: kb3 = bj; ka3 = aj; break;
                }
            }
            if (lane == 0) {
                unsigned long long ord = key >> 12;
                unsigned int n = (unsigned int)(key & 4095u);
                g_cand[b][c * MAXDET + kept] =
                    (ord << 15) | (unsigned int)((c << 12) | n);
            }
            kept++;
        }

        keyA = keyB; bA = bN; keyB = keyC;
    }

    // pad unused slots (sort last; decoded as "no detection")
    for (int t = kept + lane; t < MAXDET; t += 32)
        g_cand[b][c * MAXDET + t] = 0xFFFFFFFFFFFFFFFFull;
}

// ---- per-batch: sort 800 candidates, take top-100, write outputs ----------------
using TopSort = cub::BlockRadixSort<unsigned long long, 256, 4>;

__global__ __launch_bounds__(256) void topk_kernel(const float* __restrict__ boxes,
                                                   const float* __restrict__ rot,
                                                   const float* __restrict__ trans,
                                                   float* __restrict__ out) {
    __shared__ typename TopSort::TempStorage tmp;
    __shared__ unsigned long long sk[1024];
    int b = blockIdx.x;
    int tid = threadIdx.x;

    unsigned long long keys[4];
#pragma unroll
    for (int e = 0; e < 4; e++) {
        int idx = tid * 4 + e;
        keys[e] = (idx < CC * MAXDET) ? g_cand[b][idx] : 0xFFFFFFFFFFFFFFFFull;
    }
    TopSort(tmp).Sort(keys, 0, 47);
#pragma unroll
    for (int e = 0; e < 4; e++) sk[tid * 4 + e] = keys[e];
    __syncthreads();

    if (tid < MAXDET) {
        unsigned long long key = sk[tid];
        bool ok = (key != 0xFFFFFFFFFFFFFFFFull);
        float b0 = -1.f, b1 = -1.f, b2 = -1.f, b3 = -1.f;
        float sc = -1.f, lab = -1.f;
        float r0 = -1.f, r1 = -1.f, r2 = -1.f;
        float t0 = -1.f, t1 = -1.f, t2 = -1.f;
        if (ok) {
            unsigned int ordv = (unsigned int)(key >> 15);
            int c = (int)((key >> 12) & 7u);
            int n = (int)(key & 4095u);
            // ordv = ford(-s), -s<0 => bits(-s) = ~ordv => s = -as_float(~ordv)
            sc = -__uint_as_float(~ordv);
            lab = (float)c;
            float4 bb4 = reinterpret_cast<const float4*>(boxes)[(b << 12) + n];
            b0 = bb4.x; b1 = bb4.y; b2 = bb4.z; b3 = bb4.w;
            int base3 = ((b << 12) + n) * 3;
            r0 = rot[base3 + 0]; r1 = rot[base3 + 1]; r2 = rot[base3 + 2];
            t0 = trans[base3 + 0]; t1 = trans[base3 + 1]; t2 = trans[base3 + 2];
        }
        // output layout: boxes[B,100,4] | scores[B,100] | labels[B,100] | rot[B,100,3] | trans[B,100,3]
        int r = tid;
        float* obox = out;                       // 0    .. 800
        float* osc  = out + BB * MAXDET * 4;     // 800  .. 1000
        float* olab = osc + BB * MAXDET;         // 1000 .. 1200
        float* orot = olab + BB * MAXDET;        // 1200 .. 1800
        float* otr  = orot + BB * MAXDET * 3;    // 1800 .. 2400
        obox[(b * MAXDET + r) * 4 + 0] = b0;
        obox[(b * MAXDET + r) * 4 + 1] = b1;
        obox[(b * MAXDET + r) * 4 + 2] = b2;
        obox[(b * MAXDET + r) * 4 + 3] = b3;
        osc[b * MAXDET + r] = sc;
        olab[b * MAXDET + r] = lab;
        orot[(b * MAXDET + r) * 3 + 0] = r0;
        orot[(b * MAXDET + r) * 3 + 1] = r1;
        orot[(b * MAXDET + r) * 3 + 2] = r2;
        otr[(b * MAXDET + r) * 3 + 0] = t0;
        otr[(b * MAXDET + r) * 3 + 1] = t1;
        otr[(b * MAXDET + r) * 3 + 2] = t2;
    }
}

extern "C" void kernel_launch(void* const* d_in, const int* in_sizes, int n_in,
                              void* d_out, int out_size) {
    const float* boxes = (const float*)d_in[0];
    const float* cls   = (const float*)d_in[1];
    const float* rot   = (const float*)d_in[2];
    const float* trans = (const float*)d_in[3];
    float* out = (float*)d_out;
    (void)in_sizes; (void)n_in; (void)out_size;

    int smem1 = NN * 8 + (int)sizeof(typename BlockSort::TempStorage);
    cudaFuncSetAttribute(sortnms_kernel,
                         cudaFuncAttributeMaxDynamicSharedMemorySize, smem1);

    sortnms_kernel<<<PP, 1024, smem1>>>(cls, boxes);
    topk_kernel<<<BB, 256>>>(boxes, rot, trans, out);
}